// round 4
// baseline (speedup 1.0000x reference)
#include <cuda_runtime.h>
#include <cstdint>

// Problem shape constants (fixed by setup_inputs)
#define B_ 32
#define M_ 512
#define L_ 128
#define N_ 64
#define T_ 40
#define A_ 6
#define Z_ 64
#define C_ 3

static __device__ __constant__ float kEPS = 1e-8f;

// Scratch: fused frenet constant per (b,n):  frenet·u_ctx_w + u_ctx_b
__device__ float g_fdot[B_ * N_];

// ---------------------------------------------------------------------------
// Kernel 1: one warp per (b,n). Project pts[b,n] onto gathered polyline
// map_polylines[b, idx[b,n]] (L=128 points, 127 segments), compute
// frenet = (s/50, d/3.6, tan_x), store frenet·w + bias.
// Each lane owns 4 consecutive segments; warp-scan for cumulative arclength,
// warp argmin with first-index tiebreak (matches jnp.argmin).
// ---------------------------------------------------------------------------
__global__ void frenet_kernel(const float* __restrict__ poly,
                              const int* __restrict__ idx,
                              const float* __restrict__ pts,
                              const float* __restrict__ w,
                              const float* __restrict__ bias) {
    const int gw   = (blockIdx.x * blockDim.x + threadIdx.x) >> 5;  // (b*N+n)
    const int lane = threadIdx.x & 31;
    if (gw >= B_ * N_) return;

    const int b   = gw >> 6;   // N_ = 64
    const int pid = __ldg(idx + gw);
    const float* pl = poly + (((size_t)b * M_ + (size_t)pid) * L_) * 2;
    const float px = __ldg(pts + 2 * gw);
    const float py = __ldg(pts + 2 * gw + 1);

    float segl[4], tcl[4], dd[4], sgnd[4], tanx[4], lpre[4];
    float lsum = 0.f;

#pragma unroll
    for (int k = 0; k < 4; ++k) {
        const int j = 4 * lane + k;
        const bool valid = (j < L_ - 1);
        float2 p0 = make_float2(0.f, 0.f), p1 = make_float2(0.f, 0.f);
        if (valid) {
            p0 = *reinterpret_cast<const float2*>(pl + 2 * j);
            p1 = *reinterpret_cast<const float2*>(pl + 2 * j + 2);
        }
        const float vx = p1.x - p0.x, vy = p1.y - p0.y;
        const float v2 = fmaxf(vx * vx + vy * vy, kEPS);
        const float sl = valid ? sqrtf(v2) : 0.f;
        const float wx = px - p0.x, wy = py - p0.y;
        const float tt = fminf(fmaxf((wx * vx + wy * vy) / v2, 0.f), 1.f);
        const float dx = wx - tt * vx, dy = wy - tt * vy;
        const float q  = dx * dx + dy * dy;
        dd[k] = valid ? q : 3.0e38f;
        const float cross = vx * dy - vy * dx;
        const float sg = (cross > 0.f) ? 1.f : ((cross < 0.f) ? -1.f : 1.f);
        sgnd[k] = sg * sqrtf(fmaxf(q, kEPS));
        tanx[k] = vx / fmaxf(sl, kEPS);
        segl[k] = sl;
        tcl[k]  = tt;
        lpre[k] = lsum;
        lsum += sl;
    }

    // Warp-level exclusive prefix sum of per-lane segment-length totals
    float run = lsum;
#pragma unroll
    for (int off = 1; off < 32; off <<= 1) {
        const float v = __shfl_up_sync(0xffffffffu, run, off);
        if (lane >= off) run += v;
    }
    const float excl = run - lsum;

    // Per-lane best (k ascending -> first-index within lane)
    float bd = 3.4e38f, bs = 0.f, bdd = 0.f, bt = 0.f;
    int   bj = 1 << 30;
#pragma unroll
    for (int k = 0; k < 4; ++k) {
        const float s = excl + lpre[k] + tcl[k] * segl[k];
        if (dd[k] < bd) {
            bd = dd[k]; bj = 4 * lane + k; bs = s; bdd = sgnd[k]; bt = tanx[k];
        }
    }
    // Warp argmin with first-index tiebreak
#pragma unroll
    for (int off = 16; off > 0; off >>= 1) {
        const float od  = __shfl_xor_sync(0xffffffffu, bd, off);
        const int   oj  = __shfl_xor_sync(0xffffffffu, bj, off);
        const float os  = __shfl_xor_sync(0xffffffffu, bs, off);
        const float odd = __shfl_xor_sync(0xffffffffu, bdd, off);
        const float ot  = __shfl_xor_sync(0xffffffffu, bt, off);
        if (od < bd || (od == bd && oj < bj)) {
            bd = od; bj = oj; bs = os; bdd = odd; bt = ot;
        }
    }

    if (lane == 0) {
        const float w0 = __ldg(w), w1 = __ldg(w + 1), w2 = __ldg(w + 2);
        g_fdot[gw] = (bs * (1.f / 50.f)) * w0 + (bdd * (1.f / 3.6f)) * w1 + bt * w2
                     + __ldg(bias);
    }
}

// ---------------------------------------------------------------------------
// Kernel 2: one warp per (b,n,t). Streams decision_features (dominant HBM
// traffic), computes the 6 action dots over Z=64 via float2 per lane +
// butterfly reductions, then the masked-mean-centered utility u, and writes
// the 6 logits from lanes 0..5.
// ---------------------------------------------------------------------------
__global__ void logits_kernel(const float* __restrict__ df,
                              const float* __restrict__ ctx,
                              const int* __restrict__ fa,
                              const float* __restrict__ z,
                              const float* __restrict__ w,
                              float* __restrict__ out) {
    const int gw   = (blockIdx.x * blockDim.x + threadIdx.x) >> 5;  // (b*N+n)*T+t
    const int lane = threadIdx.x & 31;
    if (gw >= B_ * N_ * T_) return;
    const int bn = gw / T_;

    const float2 z2 = *reinterpret_cast<const float2*>(z + (size_t)bn * Z_ + 2 * lane);
    const float* dfb = df + (size_t)gw * (A_ * Z_) + 2 * lane;

    // Issue all 6 coalesced 256B loads before consuming -> MLP = 6/warp
    float acc[A_];
#pragma unroll
    for (int a = 0; a < A_; ++a) {
        const float2 v = *reinterpret_cast<const float2*>(dfb + a * Z_);
        acc[a] = v.x * z2.x + v.y * z2.y;
    }
#pragma unroll
    for (int a = 0; a < A_; ++a) {
#pragma unroll
        for (int off = 16; off > 0; off >>= 1)
            acc[a] += __shfl_xor_sync(0xffffffffu, acc[a], off);
    }

    // u = ctx·w + (frenet·w + b) : 18 contiguous ctx floats, coalesced by lanes 0..17
    const size_t cb = (size_t)gw * (A_ * C_);
    const float cv = (lane < A_ * C_) ? __ldg(ctx + cb + lane) : 0.f;
    const int   c  = lane % 3;
    const float wc = (c == 0) ? __ldg(w) : ((c == 1) ? __ldg(w + 1) : __ldg(w + 2));
    const float p  = cv * wc;
    const float p0 = __shfl_sync(0xffffffffu, p, (3 * lane) & 31);
    const float p1 = __shfl_sync(0xffffffffu, p, (3 * lane + 1) & 31);
    const float p2 = __shfl_sync(0xffffffffu, p, (3 * lane + 2) & 31);
    const float u  = p0 + p1 + p2 + g_fdot[bn];

    // Feasibility mask + mean subtraction
    const int f = (lane < A_) ? __ldg(fa + (size_t)gw * A_ + lane) : 0;
    const unsigned fm = __ballot_sync(0xffffffffu, (f != 0) && (lane < A_));
    const unsigned em = fm ? fm : 0x3fu;   // no feasible action -> all feasible
    const int cnt = __popc(em);
    float uv = ((em >> lane) & 1u) ? u : 0.f;
#pragma unroll
    for (int off = 16; off > 0; off >>= 1)
        uv += __shfl_xor_sync(0xffffffffu, uv, off);
    const float umean = uv / fmaxf((float)cnt, 1e-6f);

    if (lane < A_) {
        const float dsel = (lane == 0) ? acc[0]
                         : (lane == 1) ? acc[1]
                         : (lane == 2) ? acc[2]
                         : (lane == 3) ? acc[3]
                         : (lane == 4) ? acc[4]
                         : acc[5];
        out[(size_t)gw * A_ + lane] = dsel + (u - umean);
    }
}

// ---------------------------------------------------------------------------
// kernel_launch: inputs in metadata order:
//   0 map_polylines (B,M,L,2) f32   1 idx (B,N) i32       2 pts (B,N,2) f32
//   3 z (B,N,Z) f32                 4 decision_features (B,N,T,A,Z) f32
//   5 ctx_features (B,N,T,A,C) f32  6 feasible_actions (B,N,T,A) i32
//   7 u_ctx_w (C,) f32              8 u_ctx_b (1,) f32
// output: logits (B,N,T,A) f32
// ---------------------------------------------------------------------------
extern "C" void kernel_launch(void* const* d_in, const int* in_sizes, int n_in,
                              void* d_out, int out_size) {
    const float* poly = (const float*)d_in[0];
    const int*   idx  = (const int*)  d_in[1];
    const float* pts  = (const float*)d_in[2];
    const float* z    = (const float*)d_in[3];
    const float* df   = (const float*)d_in[4];
    const float* ctx  = (const float*)d_in[5];
    const int*   fa   = (const int*)  d_in[6];
    const float* w    = (const float*)d_in[7];
    const float* bias = (const float*)d_in[8];
    float* out = (float*)d_out;

    // 2048 warps, 8 warps/block -> 256 blocks
    frenet_kernel<<<(B_ * N_ * 32) / 256, 256>>>(poly, idx, pts, w, bias);
    // 81920 warps, 8 warps/block -> 10240 blocks
    logits_kernel<<<(B_ * N_ * T_ * 32) / 256, 256>>>(df, ctx, fa, z, w, out);
}

// round 5
// speedup vs baseline: 1.0437x; 1.0437x over previous
#include <cuda_runtime.h>
#include <cstdint>

// Problem shape constants (fixed by setup_inputs)
#define B_ 32
#define M_ 512
#define L_ 128
#define N_ 64
#define T_ 40
#define A_ 6
#define Z_ 64
#define C_ 3

#define WARPS_PER_BLOCK 8   // 40 t's = exactly 5 blocks per (b,n)

static __device__ __constant__ float kEPS = 1e-8f;

// ---------------------------------------------------------------------------
// Fused kernel. One warp per (b,n,t); 8 warps/block; every block covers
// exactly one (b,n) (since T=40 = 5 * 8). Warp 0 of each block computes the
// frenet projection for this (b,n) into shared memory (5x redundant across
// the 5 blocks of a bn — cheap, mostly L2 hits), then all warps stream
// decision_features (the dominant HBM traffic).
// ---------------------------------------------------------------------------
__global__ __launch_bounds__(32 * WARPS_PER_BLOCK)
void fused_logits_kernel(const float* __restrict__ poly,
                         const int* __restrict__ idx,
                         const float* __restrict__ pts,
                         const float* __restrict__ z,
                         const float* __restrict__ df,
                         const float* __restrict__ ctx,
                         const int* __restrict__ fa,
                         const float* __restrict__ w,
                         const float* __restrict__ bias,
                         float* __restrict__ out) {
    const int lane = threadIdx.x & 31;
    const int warp = threadIdx.x >> 5;
    const int bn   = blockIdx.x / 5;                 // (b*N + n)
    const int t    = (blockIdx.x % 5) * WARPS_PER_BLOCK + warp;
    const int gw   = bn * T_ + t;                    // (b*N+n)*T + t

    __shared__ float s_fdot;   // frenet·u_ctx_w + u_ctx_b for this bn

    const float w0 = __ldg(w), w1 = __ldg(w + 1), w2 = __ldg(w + 2);

    // ---------- warp 0: frenet projection for this bn ----------
    if (warp == 0) {
        const int b   = bn >> 6;                     // N_ = 64
        const int pid = __ldg(idx + bn);
        const float* pl = poly + (((size_t)b * M_ + (size_t)pid) * L_) * 2;
        const float px = __ldg(pts + 2 * bn);
        const float py = __ldg(pts + 2 * bn + 1);

        float segl[4], tcl[4], dd[4], sgnd[4], tanx[4], lpre[4];
        float lsum = 0.f;
#pragma unroll
        for (int k = 0; k < 4; ++k) {
            const int j = 4 * lane + k;
            const bool valid = (j < L_ - 1);
            float2 p0 = make_float2(0.f, 0.f), p1 = make_float2(0.f, 0.f);
            if (valid) {
                p0 = *reinterpret_cast<const float2*>(pl + 2 * j);
                p1 = *reinterpret_cast<const float2*>(pl + 2 * j + 2);
            }
            const float vx = p1.x - p0.x, vy = p1.y - p0.y;
            const float v2 = fmaxf(vx * vx + vy * vy, kEPS);
            const float sl = valid ? sqrtf(v2) : 0.f;
            const float wx = px - p0.x, wy = py - p0.y;
            const float tt = fminf(fmaxf((wx * vx + wy * vy) / v2, 0.f), 1.f);
            const float dx = wx - tt * vx, dy = wy - tt * vy;
            const float q  = dx * dx + dy * dy;
            dd[k] = valid ? q : 3.0e38f;
            const float cross = vx * dy - vy * dx;
            const float sg = (cross > 0.f) ? 1.f : ((cross < 0.f) ? -1.f : 1.f);
            sgnd[k] = sg * sqrtf(fmaxf(q, kEPS));
            tanx[k] = vx / fmaxf(sl, kEPS);
            segl[k] = sl;
            tcl[k]  = tt;
            lpre[k] = lsum;
            lsum += sl;
        }
        // exclusive warp prefix sum of per-lane length totals
        float run = lsum;
#pragma unroll
        for (int off = 1; off < 32; off <<= 1) {
            const float v = __shfl_up_sync(0xffffffffu, run, off);
            if (lane >= off) run += v;
        }
        const float excl = run - lsum;

        float bd = 3.4e38f, bs = 0.f, bdd = 0.f, bt = 0.f;
        int   bj = 1 << 30;
#pragma unroll
        for (int k = 0; k < 4; ++k) {
            const float s = excl + lpre[k] + tcl[k] * segl[k];
            if (dd[k] < bd) {
                bd = dd[k]; bj = 4 * lane + k; bs = s; bdd = sgnd[k]; bt = tanx[k];
            }
        }
#pragma unroll
        for (int off = 16; off > 0; off >>= 1) {
            const float od  = __shfl_xor_sync(0xffffffffu, bd, off);
            const int   oj  = __shfl_xor_sync(0xffffffffu, bj, off);
            const float os  = __shfl_xor_sync(0xffffffffu, bs, off);
            const float odd = __shfl_xor_sync(0xffffffffu, bdd, off);
            const float ot  = __shfl_xor_sync(0xffffffffu, bt, off);
            if (od < bd || (od == bd && oj < bj)) {
                bd = od; bj = oj; bs = os; bdd = odd; bt = ot;
            }
        }
        if (lane == 0) {
            s_fdot = (bs * (1.f / 50.f)) * w0 + (bdd * (1.f / 3.6f)) * w1
                     + bt * w2 + __ldg(bias);
        }
    }
    __syncthreads();
    const float fdot = s_fdot;

    // ---------- logits for (bn, t) ----------
    const int h = lane >> 4;      // half: 0 -> even actions, 1 -> odd actions
    const int q = lane & 15;

    // z as float4 per lane, replicated across halves
    const float4 z4 = *reinterpret_cast<const float4*>(z + (size_t)bn * Z_ + 4 * q);

    // 3 coalesced 512B loads: pair p covers actions (2p, 2p+1)
    const float* dfb = df + (size_t)gw * (A_ * Z_) + 4 * lane;
    float4 v[3];
#pragma unroll
    for (int p = 0; p < 3; ++p)
        v[p] = *reinterpret_cast<const float4*>(dfb + p * 2 * Z_);

    float acc[3];
#pragma unroll
    for (int p = 0; p < 3; ++p)
        acc[p] = v[p].x * z4.x + v[p].y * z4.y + v[p].z * z4.z + v[p].w * z4.w;

    // 4-level butterfly within each 16-lane half:
    // afterwards every lane in half h holds the full sum for action 2p+h
#pragma unroll
    for (int p = 0; p < 3; ++p) {
#pragma unroll
        for (int off = 8; off > 0; off >>= 1)
            acc[p] += __shfl_xor_sync(0xffffffffu, acc[p], off);
    }

    // u = ctx·w + fdot. ctx: 18 contiguous floats, lanes 0..17 coalesced.
    const size_t cb = (size_t)gw * (A_ * C_);
    const float cv = (lane < A_ * C_) ? __ldg(ctx + cb + lane) : 0.f;
    const int   c  = lane % 3;
    const float wc = (c == 0) ? w0 : ((c == 1) ? w1 : w2);
    const float pterm = cv * wc;
    // segmented 3-sum: valid at lanes 3a (a = 0..5)
    const float qs = pterm + __shfl_down_sync(0xffffffffu, pterm, 1)
                           + __shfl_down_sync(0xffffffffu, pterm, 2);
    // lane in half h picks up u for its actions 2r+h (r = 0..2)
    float ua[3];
#pragma unroll
    for (int r = 0; r < 3; ++r)
        ua[r] = __shfl_sync(0xffffffffu, qs, 3 * (2 * r + h)) + fdot;

    // feasibility mask + masked mean
    const int f = (lane < A_) ? __ldg(fa + (size_t)gw * A_ + lane) : 0;
    const unsigned fm = __ballot_sync(0xffffffffu, (f != 0) && (lane < A_));
    const unsigned em = fm ? fm : 0x3fu;
    const int cnt = __popc(em);
    float part = 0.f;
#pragma unroll
    for (int r = 0; r < 3; ++r)
        part += ((em >> (2 * r + h)) & 1u) ? ua[r] : 0.f;
    // each half's `part` is uniform; cross-half add = total masked sum
    const float tot = part + __shfl_xor_sync(0xffffffffu, part, 16);
    const float umean = tot / fmaxf((float)cnt, 1e-6f);

    // lanes 0 and 16 write even/odd actions respectively
    if (q == 0) {
        float* ob = out + (size_t)gw * A_ + h;
#pragma unroll
        for (int r = 0; r < 3; ++r)
            ob[2 * r] = acc[r] + (ua[r] - umean);
    }
}

// ---------------------------------------------------------------------------
// kernel_launch: inputs in metadata order:
//   0 map_polylines (B,M,L,2) f32   1 idx (B,N) i32       2 pts (B,N,2) f32
//   3 z (B,N,Z) f32                 4 decision_features (B,N,T,A,Z) f32
//   5 ctx_features (B,N,T,A,C) f32  6 feasible_actions (B,N,T,A) i32
//   7 u_ctx_w (C,) f32              8 u_ctx_b (1,) f32
// output: logits (B,N,T,A) f32
// ---------------------------------------------------------------------------
extern "C" void kernel_launch(void* const* d_in, const int* in_sizes, int n_in,
                              void* d_out, int out_size) {
    const float* poly = (const float*)d_in[0];
    const int*   idx  = (const int*)  d_in[1];
    const float* pts  = (const float*)d_in[2];
    const float* z    = (const float*)d_in[3];
    const float* df   = (const float*)d_in[4];
    const float* ctx  = (const float*)d_in[5];
    const int*   fa   = (const int*)  d_in[6];
    const float* w    = (const float*)d_in[7];
    const float* bias = (const float*)d_in[8];
    float* out = (float*)d_out;

    // 81920 warps, 8 warps/block -> 10240 blocks, 5 blocks per (b,n)
    fused_logits_kernel<<<(B_ * N_ * T_) / WARPS_PER_BLOCK, 32 * WARPS_PER_BLOCK>>>(
        poly, idx, pts, z, df, ctx, fa, w, bias, out);
}